// round 6
// baseline (speedup 1.0000x reference)
#include <cuda_runtime.h>
#include <cuda_bf16.h>
#include <cstdint>

#define KDIM 256
#define NWARP 8

// ---------- helpers ----------
__device__ __forceinline__ uint32_t pk(float a, float b) {
    return ((uint32_t)__bfloat16_as_ushort(__float2bfloat16_rn(b)) << 16) |
           (uint32_t)__bfloat16_as_ushort(__float2bfloat16_rn(a));
}
__device__ __forceinline__ void bsplit2(float a, float b, uint32_t& hi, uint32_t& lo) {
    __nv_bfloat16 ah = __float2bfloat16_rn(a), bh = __float2bfloat16_rn(b);
    hi = ((uint32_t)__bfloat16_as_ushort(bh) << 16) | (uint32_t)__bfloat16_as_ushort(ah);
    lo = pk(a - __bfloat162float(ah), b - __bfloat162float(bh));
}
__device__ __forceinline__ void mma16816(float* c, const uint32_t* a, uint32_t b0, uint32_t b1) {
    asm volatile(
        "mma.sync.aligned.m16n8k16.row.col.f32.bf16.bf16.f32 "
        "{%0,%1,%2,%3},{%4,%5,%6,%7},{%8,%9},{%0,%1,%2,%3};"
        : "+f"(c[0]), "+f"(c[1]), "+f"(c[2]), "+f"(c[3])
        : "r"(a[0]), "r"(a[1]), "r"(a[2]), "r"(a[3]), "r"(b0), "r"(b1));
}

// SMEM layout (bytes)
#define SM_W1F 0          // uint4[16 kb][16 nb][32 lane]  = 131072
#define SM_W2F 131072     // uint4[4 m][2 kb][4 nb][32]    = 16384
#define SM_W3F 147456     // 16384
#define SM_B1  163840
#define SM_B2  164352
#define SM_B3  164864
#define SM_WF  165376
#define SM_BFV 165504
#define SMEM_BYTES 165632

extern __shared__ char smem[];

__global__ void __launch_bounds__(32 * NWARP, 1)
moe_kernel(const float* __restrict__ x,  const float* __restrict__ c1,
           const float* __restrict__ c2, const float* __restrict__ c3,
           const float* __restrict__ W1, const float* __restrict__ b1,
           const float* __restrict__ W2, const float* __restrict__ b2,
           const float* __restrict__ W3, const float* __restrict__ b3,
           const float* __restrict__ Wf, const float* __restrict__ bfp,
           float* __restrict__ out, int Btot) {
    const int tid = threadIdx.x;
    const int wid = tid >> 5;
    const int lane = tid & 31;
    const int g = lane >> 2;   // group id (row within m16 block)
    const int t = lane & 3;    // thread-in-group

    uint4* w1f = (uint4*)(smem + SM_W1F);
    uint4* w2f = (uint4*)(smem + SM_W2F);
    uint4* w3f = (uint4*)(smem + SM_W3F);
    float* b1s = (float*)(smem + SM_B1);
    float* b2s = (float*)(smem + SM_B2);
    float* b3s = (float*)(smem + SM_B3);
    float* wfs = (float*)(smem + SM_WF);
    float* bfs = (float*)(smem + SM_BFV);

    // ---- W1 fragments with K-PERMUTATION: frag slots (t*2,t*2+1 | t*2+8,t*2+9)
    //      carry data at original k = kb*16 + t*4 + (0,1 | 2,3). A side matches. ----
    for (int e = wid; e < 256; e += NWARP) {
        int kb = e >> 4, nb = e & 15;
        const float* wp = W1 + (nb * 8 + g) * 256 + kb * 16 + t * 4;
        uint32_t b0h, b0l, b1h, b1l;
        bsplit2(wp[0], wp[1], b0h, b0l);
        bsplit2(wp[2], wp[3], b1h, b1l);
        w1f[e * 32 + lane] = make_uint4(b0h, b1h, b0l, b1l);
    }
    // ---- W2/W3: identity K-mapping (matches register-local mix outputs) ----
    for (int e = wid; e < 32; e += NWARP) {
        int m = e >> 3, kb = (e >> 2) & 1, nb = e & 3;
        int off = (m * 32 + nb * 8 + g) * 32 + kb * 16 + t * 2;
        {
            const float* wp = W2 + off;
            uint32_t b0h, b0l, b1h, b1l;
            bsplit2(wp[0], wp[1], b0h, b0l);
            bsplit2(wp[8], wp[9], b1h, b1l);
            w2f[e * 32 + lane] = make_uint4(b0h, b1h, b0l, b1l);
        }
        {
            const float* wp = W3 + off;
            uint32_t b0h, b0l, b1h, b1l;
            bsplit2(wp[0], wp[1], b0h, b0l);
            bsplit2(wp[8], wp[9], b1h, b1l);
            w3f[e * 32 + lane] = make_uint4(b0h, b1h, b0l, b1l);
        }
    }
    if (tid < 128) { b1s[tid] = b1[tid]; b2s[tid] = b2[tid]; b3s[tid] = b3[tid]; }
    if (tid < 32 && wid == 0) wfs[tid] = Wf[tid];
    if (tid == 0) bfs[0] = bfp[0];
    __syncthreads();

    float wfv[4][2];
#pragma unroll
    for (int nb = 0; nb < 4; nb++) { wfv[nb][0] = wfs[nb * 8 + t * 2]; wfv[nb][1] = wfs[nb * 8 + t * 2 + 1]; }
    const float bf0 = bfs[0];

    const int gw = blockIdx.x * NWARP + wid;
    const int nunits = (Btot + 31) >> 5;

    for (int u = gw; u < nunits; u += gridDim.x * NWARP) {
        // 4 rows per thread: block0 = rows (g, g+8); block1 = (g+16, g+24)
        int r[4];
        const float* px[4];
#pragma unroll
        for (int j = 0; j < 4; j++) {
            r[j] = u * 32 + g + j * 8;
            int rc = r[j] < Btot ? r[j] : Btot - 1;
            px[j] = x + (size_t)rc * KDIM + t * 4;
        }

        // ---- stage 1: C[2 blocks][16 nb][4] over K=256, 3-pass split ----
        float c1f[2][16][4];
#pragma unroll
        for (int b = 0; b < 2; b++)
#pragma unroll
            for (int nb = 0; nb < 16; nb++)
#pragma unroll
                for (int i = 0; i < 4; i++) c1f[b][nb][i] = 0.f;

        float4 cA0, cA1, cA2, cA3, cB0, cB1, cB2, cB3;
        cA0 = *(const float4*)(px[0]); cA1 = *(const float4*)(px[1]);
        cA2 = *(const float4*)(px[2]); cA3 = *(const float4*)(px[3]);
#pragma unroll 1
        for (int kb = 0; kb < 16; kb += 2) {
            // prefetch kb+1
            cB0 = *(const float4*)(px[0] + (kb + 1) * 16);
            cB1 = *(const float4*)(px[1] + (kb + 1) * 16);
            cB2 = *(const float4*)(px[2] + (kb + 1) * 16);
            cB3 = *(const float4*)(px[3] + (kb + 1) * 16);
            {
                uint32_t ah0[4], al0[4], ah1[4], al1[4];
                bsplit2(cA0.x, cA0.y, ah0[0], al0[0]); bsplit2(cA1.x, cA1.y, ah0[1], al0[1]);
                bsplit2(cA0.z, cA0.w, ah0[2], al0[2]); bsplit2(cA1.z, cA1.w, ah0[3], al0[3]);
                bsplit2(cA2.x, cA2.y, ah1[0], al1[0]); bsplit2(cA3.x, cA3.y, ah1[1], al1[1]);
                bsplit2(cA2.z, cA2.w, ah1[2], al1[2]); bsplit2(cA3.z, cA3.w, ah1[3], al1[3]);
                const uint4* wrow = w1f + kb * 512 + lane;
#pragma unroll
                for (int nb = 0; nb < 16; nb++) {
                    uint4 w = wrow[nb * 32];
                    mma16816(c1f[0][nb], ah0, w.x, w.y);
                    mma16816(c1f[1][nb], ah1, w.x, w.y);
                    mma16816(c1f[0][nb], ah0, w.z, w.w);
                    mma16816(c1f[1][nb], ah1, w.z, w.w);
                    mma16816(c1f[0][nb], al0, w.x, w.y);
                    mma16816(c1f[1][nb], al1, w.x, w.y);
                }
            }
            // prefetch kb+2 (wrap-safe)
            int k2 = (kb + 2) & 15;
            cA0 = *(const float4*)(px[0] + k2 * 16);
            cA1 = *(const float4*)(px[1] + k2 * 16);
            cA2 = *(const float4*)(px[2] + k2 * 16);
            cA3 = *(const float4*)(px[3] + k2 * 16);
            {
                uint32_t ah0[4], al0[4], ah1[4], al1[4];
                bsplit2(cB0.x, cB0.y, ah0[0], al0[0]); bsplit2(cB1.x, cB1.y, ah0[1], al0[1]);
                bsplit2(cB0.z, cB0.w, ah0[2], al0[2]); bsplit2(cB1.z, cB1.w, ah0[3], al0[3]);
                bsplit2(cB2.x, cB2.y, ah1[0], al1[0]); bsplit2(cB3.x, cB3.y, ah1[1], al1[1]);
                bsplit2(cB2.z, cB2.w, ah1[2], al1[2]); bsplit2(cB3.z, cB3.w, ah1[3], al1[3]);
                const uint4* wrow = w1f + (kb + 1) * 512 + lane;
#pragma unroll
                for (int nb = 0; nb < 16; nb++) {
                    uint4 w = wrow[nb * 32];
                    mma16816(c1f[0][nb], ah0, w.x, w.y);
                    mma16816(c1f[1][nb], ah1, w.x, w.y);
                    mma16816(c1f[0][nb], ah0, w.z, w.w);
                    mma16816(c1f[1][nb], ah1, w.z, w.w);
                    mma16816(c1f[0][nb], al0, w.x, w.y);
                    mma16816(c1f[1][nb], al1, w.x, w.y);
                }
            }
        }

        // ---- mix1 (per block): relu(+b1), c1-mix -> A2 fragments ----
        uint32_t a2h[2][4][2][4], a2l[2][4][2][4];
#pragma unroll
        for (int b = 0; b < 2; b++) {
            int q0 = r[2 * b]     < Btot ? r[2 * b]     : Btot - 1;
            int q1 = r[2 * b + 1] < Btot ? r[2 * b + 1] : Btot - 1;
            float cc0[16], cc1[16];
            {
                const float4* a = (const float4*)(c1 + (size_t)q0 * 16);
                const float4* bb = (const float4*)(c1 + (size_t)q1 * 16);
#pragma unroll
                for (int q = 0; q < 4; q++) {
                    float4 v = a[q];
                    cc0[4 * q] = v.x; cc0[4 * q + 1] = v.y; cc0[4 * q + 2] = v.z; cc0[4 * q + 3] = v.w;
                    float4 w = bb[q];
                    cc1[4 * q] = w.x; cc1[4 * q + 1] = w.y; cc1[4 * q + 2] = w.z; cc1[4 * q + 3] = w.w;
                }
            }
#pragma unroll
            for (int hc = 0; hc < 4; hc++) {
                float o0[4][2], o1v[4][2];
#pragma unroll
                for (int n = 0; n < 4; n++) {
                    int nb = n * 4 + hc;
                    float bb0 = b1s[nb * 8 + t * 2], bb1 = b1s[nb * 8 + t * 2 + 1];
                    o0[n][0]  = fmaxf(c1f[b][nb][0] + bb0, 0.f);
                    o0[n][1]  = fmaxf(c1f[b][nb][1] + bb1, 0.f);
                    o1v[n][0] = fmaxf(c1f[b][nb][2] + bb0, 0.f);
                    o1v[n][1] = fmaxf(c1f[b][nb][3] + bb1, 0.f);
                }
                int kb2 = hc >> 1, hf = hc & 1;
#pragma unroll
                for (int m = 0; m < 4; m++) {
                    float i00 = 0.f, i01 = 0.f, i10 = 0.f, i11 = 0.f;
#pragma unroll
                    for (int n = 0; n < 4; n++) {
                        i00 = fmaf(o0[n][0],  cc0[n * 4 + m], i00);
                        i01 = fmaf(o0[n][1],  cc0[n * 4 + m], i01);
                        i10 = fmaf(o1v[n][0], cc1[n * 4 + m], i10);
                        i11 = fmaf(o1v[n][1], cc1[n * 4 + m], i11);
                    }
                    bsplit2(i00, i01, a2h[b][m][kb2][hf * 2 + 0], a2l[b][m][kb2][hf * 2 + 0]);
                    bsplit2(i10, i11, a2h[b][m][kb2][hf * 2 + 1], a2l[b][m][kb2][hf * 2 + 1]);
                }
            }
        }

        // ---- stages 2, 3 + final: per m16-block (register pressure) ----
#pragma unroll 1
        for (int b = 0; b < 2; b++) {
            int q0 = r[2 * b]     < Btot ? r[2 * b]     : Btot - 1;
            int q1 = r[2 * b + 1] < Btot ? r[2 * b + 1] : Btot - 1;

            // stage 2
            float c2f[4][4][4];
#pragma unroll
            for (int m = 0; m < 4; m++)
#pragma unroll
                for (int nb = 0; nb < 4; nb++)
#pragma unroll
                    for (int i = 0; i < 4; i++) c2f[m][nb][i] = 0.f;
#pragma unroll
            for (int m = 0; m < 4; m++)
#pragma unroll
                for (int kb = 0; kb < 2; kb++)
#pragma unroll
                    for (int nb = 0; nb < 4; nb++) {
                        uint4 w = w2f[((m * 2 + kb) * 4 + nb) * 32 + lane];
                        mma16816(c2f[m][nb], a2h[b][m][kb], w.x, w.y);
                        mma16816(c2f[m][nb], a2h[b][m][kb], w.z, w.w);
                        mma16816(c2f[m][nb], a2l[b][m][kb], w.x, w.y);
                    }

            // c2 coeffs
            float cc0[16], cc1[16];
            {
                const float4* a = (const float4*)(c2 + (size_t)q0 * 16);
                const float4* bb = (const float4*)(c2 + (size_t)q1 * 16);
#pragma unroll
                for (int q = 0; q < 4; q++) {
                    float4 v = a[q];
                    cc0[4 * q] = v.x; cc0[4 * q + 1] = v.y; cc0[4 * q + 2] = v.z; cc0[4 * q + 3] = v.w;
                    float4 w = bb[q];
                    cc1[4 * q] = w.x; cc1[4 * q + 1] = w.y; cc1[4 * q + 2] = w.z; cc1[4 * q + 3] = w.w;
                }
            }

            // mix2 -> A3
            uint32_t a3h[4][2][4], a3l[4][2][4];
#pragma unroll
            for (int hc = 0; hc < 4; hc++) {
                float o0[4][2], o1v[4][2];
#pragma unroll
                for (int n = 0; n < 4; n++) {
                    float bb0 = b2s[n * 32 + hc * 8 + t * 2], bb1 = b2s[n * 32 + hc * 8 + t * 2 + 1];
                    o0[n][0]  = fmaxf(c2f[n][hc][0] + bb0, 0.f);
                    o0[n][1]  = fmaxf(c2f[n][hc][1] + bb1, 0.f);
                    o1v[n][0] = fmaxf(c2f[n][hc][2] + bb0, 0.f);
                    o1v[n][1] = fmaxf(c2f[n][hc][3] + bb1, 0.f);
                }
                int kb2 = hc >> 1, hf = hc & 1;
#pragma unroll
                for (int m = 0; m < 4; m++) {
                    float i00 = 0.f, i01 = 0.f, i10 = 0.f, i11 = 0.f;
#pragma unroll
                    for (int n = 0; n < 4; n++) {
                        i00 = fmaf(o0[n][0],  cc0[n * 4 + m], i00);
                        i01 = fmaf(o0[n][1],  cc0[n * 4 + m], i01);
                        i10 = fmaf(o1v[n][0], cc1[n * 4 + m], i10);
                        i11 = fmaf(o1v[n][1], cc1[n * 4 + m], i11);
                    }
                    bsplit2(i00, i01, a3h[m][kb2][hf * 2 + 0], a3l[m][kb2][hf * 2 + 0]);
                    bsplit2(i10, i11, a3h[m][kb2][hf * 2 + 1], a3l[m][kb2][hf * 2 + 1]);
                }
            }

            // stage 3
            float c3f[4][4][4];
#pragma unroll
            for (int m = 0; m < 4; m++)
#pragma unroll
                for (int nb = 0; nb < 4; nb++)
#pragma unroll
                    for (int i = 0; i < 4; i++) c3f[m][nb][i] = 0.f;
#pragma unroll
            for (int m = 0; m < 4; m++)
#pragma unroll
                for (int kb = 0; kb < 2; kb++)
#pragma unroll
                    for (int nb = 0; nb < 4; nb++) {
                        uint4 w = w3f[((m * 2 + kb) * 4 + nb) * 32 + lane];
                        mma16816(c3f[m][nb], a3h[m][kb], w.x, w.y);
                        mma16816(c3f[m][nb], a3h[m][kb], w.z, w.w);
                        mma16816(c3f[m][nb], a3l[m][kb], w.x, w.y);
                    }

            // final: relu(+b3), c3 mix, Wf dot, quad reduce
            float c3c0[4], c3c1[4];
            {
                float4 v = *(const float4*)(c3 + (size_t)q0 * 4);
                c3c0[0] = v.x; c3c0[1] = v.y; c3c0[2] = v.z; c3c0[3] = v.w;
                float4 w = *(const float4*)(c3 + (size_t)q1 * 4);
                c3c1[0] = w.x; c3c1[1] = w.y; c3c1[2] = w.z; c3c1[3] = w.w;
            }
            float pa = 0.f, pb = 0.f;
#pragma unroll
            for (int nb = 0; nb < 4; nb++) {
#pragma unroll
                for (int n = 0; n < 4; n++) {
                    float bb0 = b3s[n * 32 + nb * 8 + t * 2], bb1 = b3s[n * 32 + nb * 8 + t * 2 + 1];
                    float q00 = fmaxf(c3f[n][nb][0] + bb0, 0.f);
                    float q01 = fmaxf(c3f[n][nb][1] + bb1, 0.f);
                    float q10 = fmaxf(c3f[n][nb][2] + bb0, 0.f);
                    float q11 = fmaxf(c3f[n][nb][3] + bb1, 0.f);
                    pa = fmaf(fmaf(q00, wfv[nb][0], q01 * wfv[nb][1]), c3c0[n], pa);
                    pb = fmaf(fmaf(q10, wfv[nb][0], q11 * wfv[nb][1]), c3c1[n], pb);
                }
            }
            pa += __shfl_xor_sync(0xffffffffu, pa, 1);
            pa += __shfl_xor_sync(0xffffffffu, pa, 2);
            pb += __shfl_xor_sync(0xffffffffu, pb, 1);
            pb += __shfl_xor_sync(0xffffffffu, pb, 2);
            if (t == 0) {
                if (r[2 * b]     < Btot) out[r[2 * b]]     = pa + bf0;
                if (r[2 * b + 1] < Btot) out[r[2 * b + 1]] = pb + bf0;
            }
        }
    }
}

extern "C" void kernel_launch(void* const* d_in, const int* in_sizes, int n_in,
                              void* d_out, int out_size) {
    const float* x   = (const float*)d_in[0];
    const float* c1  = (const float*)d_in[1];
    const float* c2  = (const float*)d_in[2];
    const float* c3  = (const float*)d_in[3];
    const float* W1  = (const float*)d_in[4];
    const float* b1  = (const float*)d_in[5];
    const float* W2  = (const float*)d_in[6];
    const float* b2  = (const float*)d_in[7];
    const float* W3  = (const float*)d_in[8];
    const float* b3  = (const float*)d_in[9];
    const float* Wf  = (const float*)d_in[10];
    const float* bfp = (const float*)d_in[11];
    int B = in_sizes[0] / KDIM;
    static bool configured = false;
    if (!configured) {
        cudaFuncSetAttribute(moe_kernel, cudaFuncAttributeMaxDynamicSharedMemorySize, SMEM_BYTES);
        configured = true;
    }
    moe_kernel<<<148, 32 * NWARP, SMEM_BYTES>>>(x, c1, c2, c3, W1, b1, W2, b2, W3, b3, Wf, bfp,
                                                (float*)d_out, B);
}

// round 7
// speedup vs baseline: 1.0006x; 1.0006x over previous
#include <cuda_runtime.h>
#include <cuda_bf16.h>
#include <cstdint>

#define KDIM 256
#define NWARP 8

// ---------- helpers ----------
__device__ __forceinline__ uint32_t pk(float a, float b) {
    return ((uint32_t)__bfloat16_as_ushort(__float2bfloat16_rn(b)) << 16) |
           (uint32_t)__bfloat16_as_ushort(__float2bfloat16_rn(a));
}
__device__ __forceinline__ void bsplit2(float a, float b, uint32_t& hi, uint32_t& lo) {
    __nv_bfloat16 ah = __float2bfloat16_rn(a), bh = __float2bfloat16_rn(b);
    hi = ((uint32_t)__bfloat16_as_ushort(bh) << 16) | (uint32_t)__bfloat16_as_ushort(ah);
    lo = pk(a - __bfloat162float(ah), b - __bfloat162float(bh));
}
__device__ __forceinline__ void mma16816(float* c, const uint32_t* a, uint32_t b0, uint32_t b1) {
    asm volatile(
        "mma.sync.aligned.m16n8k16.row.col.f32.bf16.bf16.f32 "
        "{%0,%1,%2,%3},{%4,%5,%6,%7},{%8,%9},{%0,%1,%2,%3};"
        : "+f"(c[0]), "+f"(c[1]), "+f"(c[2]), "+f"(c[3])
        : "r"(a[0]), "r"(a[1]), "r"(a[2]), "r"(a[3]), "r"(b0), "r"(b1));
}

// SMEM layout (bytes)
#define SM_W1F 0          // uint4[16 kb][16 nb][32 lane]  = 131072
#define SM_W2F 131072     // uint4[4 m][2 kb][4 nb][32]    = 16384
#define SM_W3F 147456     // 16384
#define SM_B1  163840
#define SM_B2  164352
#define SM_B3  164864
#define SM_WF  165376
#define SM_BFV 165504
#define SMEM_BYTES 165632

extern __shared__ char smem[];

__global__ void __launch_bounds__(32 * NWARP, 1)
moe_kernel(const float* __restrict__ x,  const float* __restrict__ c1,
           const float* __restrict__ c2, const float* __restrict__ c3,
           const float* __restrict__ W1, const float* __restrict__ b1,
           const float* __restrict__ W2, const float* __restrict__ b2,
           const float* __restrict__ W3, const float* __restrict__ b3,
           const float* __restrict__ Wf, const float* __restrict__ bfp,
           float* __restrict__ out, int Btot) {
    const int tid = threadIdx.x;
    const int wid = tid >> 5;
    const int lane = tid & 31;
    const int g = lane >> 2;   // group id (row within m16 block)
    const int t = lane & 3;    // thread-in-group

    uint4* w1f = (uint4*)(smem + SM_W1F);
    uint4* w2f = (uint4*)(smem + SM_W2F);
    uint4* w3f = (uint4*)(smem + SM_W3F);
    float* b1s = (float*)(smem + SM_B1);
    float* b2s = (float*)(smem + SM_B2);
    float* b3s = (float*)(smem + SM_B3);
    float* wfs = (float*)(smem + SM_WF);
    float* bfs = (float*)(smem + SM_BFV);

    // ---- W1 fragments with K-PERMUTATION: frag slots (t*2,t*2+1 | t*2+8,t*2+9)
    //      carry data at original k = kb*16 + t*4 + (0,1 | 2,3). A side matches. ----
    for (int e = wid; e < 256; e += NWARP) {
        int kb = e >> 4, nb = e & 15;
        const float* wp = W1 + (nb * 8 + g) * 256 + kb * 16 + t * 4;
        uint32_t b0h, b0l, b1h, b1l;
        bsplit2(wp[0], wp[1], b0h, b0l);
        bsplit2(wp[2], wp[3], b1h, b1l);
        w1f[e * 32 + lane] = make_uint4(b0h, b1h, b0l, b1l);
    }
    // ---- W2/W3: identity K-mapping (matches register-local mix outputs) ----
    for (int e = wid; e < 32; e += NWARP) {
        int m = e >> 3, kb = (e >> 2) & 1, nb = e & 3;
        int off = (m * 32 + nb * 8 + g) * 32 + kb * 16 + t * 2;
        {
            const float* wp = W2 + off;
            uint32_t b0h, b0l, b1h, b1l;
            bsplit2(wp[0], wp[1], b0h, b0l);
            bsplit2(wp[8], wp[9], b1h, b1l);
            w2f[e * 32 + lane] = make_uint4(b0h, b1h, b0l, b1l);
        }
        {
            const float* wp = W3 + off;
            uint32_t b0h, b0l, b1h, b1l;
            bsplit2(wp[0], wp[1], b0h, b0l);
            bsplit2(wp[8], wp[9], b1h, b1l);
            w3f[e * 32 + lane] = make_uint4(b0h, b1h, b0l, b1l);
        }
    }
    if (tid < 128) { b1s[tid] = b1[tid]; b2s[tid] = b2[tid]; b3s[tid] = b3[tid]; }
    if (tid < 32 && wid == 0) wfs[tid] = Wf[tid];
    if (tid == 0) bfs[0] = bfp[0];
    __syncthreads();

    float wfv[4][2];
#pragma unroll
    for (int nb = 0; nb < 4; nb++) { wfv[nb][0] = wfs[nb * 8 + t * 2]; wfv[nb][1] = wfs[nb * 8 + t * 2 + 1]; }
    const float bf0 = bfs[0];

    const int gw = blockIdx.x * NWARP + wid;
    const int nunits = (Btot + 31) >> 5;

    for (int u = gw; u < nunits; u += gridDim.x * NWARP) {
        // 4 rows per thread: block0 = rows (g, g+8); block1 = (g+16, g+24)
        int r[4];
        const float* px[4];
#pragma unroll
        for (int j = 0; j < 4; j++) {
            r[j] = u * 32 + g + j * 8;
            int rc = r[j] < Btot ? r[j] : Btot - 1;
            px[j] = x + (size_t)rc * KDIM + t * 4;
        }

        // ---- stage 1: C[2 blocks][16 nb][4] over K=256, 3-pass split ----
        float c1f[2][16][4];
#pragma unroll
        for (int b = 0; b < 2; b++)
#pragma unroll
            for (int nb = 0; nb < 16; nb++)
#pragma unroll
                for (int i = 0; i < 4; i++) c1f[b][nb][i] = 0.f;

        float4 cA0, cA1, cA2, cA3, cB0, cB1, cB2, cB3;
        cA0 = *(const float4*)(px[0]); cA1 = *(const float4*)(px[1]);
        cA2 = *(const float4*)(px[2]); cA3 = *(const float4*)(px[3]);
#pragma unroll 1
        for (int kb = 0; kb < 16; kb += 2) {
            // prefetch kb+1
            cB0 = *(const float4*)(px[0] + (kb + 1) * 16);
            cB1 = *(const float4*)(px[1] + (kb + 1) * 16);
            cB2 = *(const float4*)(px[2] + (kb + 1) * 16);
            cB3 = *(const float4*)(px[3] + (kb + 1) * 16);
            {
                uint32_t ah0[4], al0[4], ah1[4], al1[4];
                bsplit2(cA0.x, cA0.y, ah0[0], al0[0]); bsplit2(cA1.x, cA1.y, ah0[1], al0[1]);
                bsplit2(cA0.z, cA0.w, ah0[2], al0[2]); bsplit2(cA1.z, cA1.w, ah0[3], al0[3]);
                bsplit2(cA2.x, cA2.y, ah1[0], al1[0]); bsplit2(cA3.x, cA3.y, ah1[1], al1[1]);
                bsplit2(cA2.z, cA2.w, ah1[2], al1[2]); bsplit2(cA3.z, cA3.w, ah1[3], al1[3]);
                const uint4* wrow = w1f + kb * 512 + lane;
#pragma unroll
                for (int nb = 0; nb < 16; nb++) {
                    uint4 w = wrow[nb * 32];
                    mma16816(c1f[0][nb], ah0, w.x, w.y);
                    mma16816(c1f[1][nb], ah1, w.x, w.y);
                    mma16816(c1f[0][nb], ah0, w.z, w.w);
                    mma16816(c1f[1][nb], ah1, w.z, w.w);
                    mma16816(c1f[0][nb], al0, w.x, w.y);
                    mma16816(c1f[1][nb], al1, w.x, w.y);
                }
            }
            // prefetch kb+2 (wrap-safe)
            int k2 = (kb + 2) & 15;
            cA0 = *(const float4*)(px[0] + k2 * 16);
            cA1 = *(const float4*)(px[1] + k2 * 16);
            cA2 = *(const float4*)(px[2] + k2 * 16);
            cA3 = *(const float4*)(px[3] + k2 * 16);
            {
                uint32_t ah0[4], al0[4], ah1[4], al1[4];
                bsplit2(cB0.x, cB0.y, ah0[0], al0[0]); bsplit2(cB1.x, cB1.y, ah0[1], al0[1]);
                bsplit2(cB0.z, cB0.w, ah0[2], al0[2]); bsplit2(cB1.z, cB1.w, ah0[3], al0[3]);
                bsplit2(cB2.x, cB2.y, ah1[0], al1[0]); bsplit2(cB3.x, cB3.y, ah1[1], al1[1]);
                bsplit2(cB2.z, cB2.w, ah1[2], al1[2]); bsplit2(cB3.z, cB3.w, ah1[3], al1[3]);
                const uint4* wrow = w1f + (kb + 1) * 512 + lane;
#pragma unroll
                for (int nb = 0; nb < 16; nb++) {
                    uint4 w = wrow[nb * 32];
                    mma16816(c1f[0][nb], ah0, w.x, w.y);
                    mma16816(c1f[1][nb], ah1, w.x, w.y);
                    mma16816(c1f[0][nb], ah0, w.z, w.w);
                    mma16816(c1f[1][nb], ah1, w.z, w.w);
                    mma16816(c1f[0][nb], al0, w.x, w.y);
                    mma16816(c1f[1][nb], al1, w.x, w.y);
                }
            }
        }

        // ---- mix1 (per block): relu(+b1), c1-mix -> A2 fragments ----
        uint32_t a2h[2][4][2][4], a2l[2][4][2][4];
#pragma unroll
        for (int b = 0; b < 2; b++) {
            int q0 = r[2 * b]     < Btot ? r[2 * b]     : Btot - 1;
            int q1 = r[2 * b + 1] < Btot ? r[2 * b + 1] : Btot - 1;
            float cc0[16], cc1[16];
            {
                const float4* a = (const float4*)(c1 + (size_t)q0 * 16);
                const float4* bb = (const float4*)(c1 + (size_t)q1 * 16);
#pragma unroll
                for (int q = 0; q < 4; q++) {
                    float4 v = a[q];
                    cc0[4 * q] = v.x; cc0[4 * q + 1] = v.y; cc0[4 * q + 2] = v.z; cc0[4 * q + 3] = v.w;
                    float4 w = bb[q];
                    cc1[4 * q] = w.x; cc1[4 * q + 1] = w.y; cc1[4 * q + 2] = w.z; cc1[4 * q + 3] = w.w;
                }
            }
#pragma unroll
            for (int hc = 0; hc < 4; hc++) {
                float o0[4][2], o1v[4][2];
#pragma unroll
                for (int n = 0; n < 4; n++) {
                    int nb = n * 4 + hc;
                    float bb0 = b1s[nb * 8 + t * 2], bb1 = b1s[nb * 8 + t * 2 + 1];
                    o0[n][0]  = fmaxf(c1f[b][nb][0] + bb0, 0.f);
                    o0[n][1]  = fmaxf(c1f[b][nb][1] + bb1, 0.f);
                    o1v[n][0] = fmaxf(c1f[b][nb][2] + bb0, 0.f);
                    o1v[n][1] = fmaxf(c1f[b][nb][3] + bb1, 0.f);
                }
                int kb2 = hc >> 1, hf = hc & 1;
#pragma unroll
                for (int m = 0; m < 4; m++) {
                    float i00 = 0.f, i01 = 0.f, i10 = 0.f, i11 = 0.f;
#pragma unroll
                    for (int n = 0; n < 4; n++) {
                        i00 = fmaf(o0[n][0],  cc0[n * 4 + m], i00);
                        i01 = fmaf(o0[n][1],  cc0[n * 4 + m], i01);
                        i10 = fmaf(o1v[n][0], cc1[n * 4 + m], i10);
                        i11 = fmaf(o1v[n][1], cc1[n * 4 + m], i11);
                    }
                    bsplit2(i00, i01, a2h[b][m][kb2][hf * 2 + 0], a2l[b][m][kb2][hf * 2 + 0]);
                    bsplit2(i10, i11, a2h[b][m][kb2][hf * 2 + 1], a2l[b][m][kb2][hf * 2 + 1]);
                }
            }
        }

        // ---- stages 2, 3 + final: per m16-block (register pressure) ----
#pragma unroll 1
        for (int b = 0; b < 2; b++) {
            int q0 = r[2 * b]     < Btot ? r[2 * b]     : Btot - 1;
            int q1 = r[2 * b + 1] < Btot ? r[2 * b + 1] : Btot - 1;

            // stage 2
            float c2f[4][4][4];
#pragma unroll
            for (int m = 0; m < 4; m++)
#pragma unroll
                for (int nb = 0; nb < 4; nb++)
#pragma unroll
                    for (int i = 0; i < 4; i++) c2f[m][nb][i] = 0.f;
#pragma unroll
            for (int m = 0; m < 4; m++)
#pragma unroll
                for (int kb = 0; kb < 2; kb++)
#pragma unroll
                    for (int nb = 0; nb < 4; nb++) {
                        uint4 w = w2f[((m * 2 + kb) * 4 + nb) * 32 + lane];
                        mma16816(c2f[m][nb], a2h[b][m][kb], w.x, w.y);
                        mma16816(c2f[m][nb], a2h[b][m][kb], w.z, w.w);
                        mma16816(c2f[m][nb], a2l[b][m][kb], w.x, w.y);
                    }

            // c2 coeffs
            float cc0[16], cc1[16];
            {
                const float4* a = (const float4*)(c2 + (size_t)q0 * 16);
                const float4* bb = (const float4*)(c2 + (size_t)q1 * 16);
#pragma unroll
                for (int q = 0; q < 4; q++) {
                    float4 v = a[q];
                    cc0[4 * q] = v.x; cc0[4 * q + 1] = v.y; cc0[4 * q + 2] = v.z; cc0[4 * q + 3] = v.w;
                    float4 w = bb[q];
                    cc1[4 * q] = w.x; cc1[4 * q + 1] = w.y; cc1[4 * q + 2] = w.z; cc1[4 * q + 3] = w.w;
                }
            }

            // mix2 -> A3
            uint32_t a3h[4][2][4], a3l[4][2][4];
#pragma unroll
            for (int hc = 0; hc < 4; hc++) {
                float o0[4][2], o1v[4][2];
#pragma unroll
                for (int n = 0; n < 4; n++) {
                    float bb0 = b2s[n * 32 + hc * 8 + t * 2], bb1 = b2s[n * 32 + hc * 8 + t * 2 + 1];
                    o0[n][0]  = fmaxf(c2f[n][hc][0] + bb0, 0.f);
                    o0[n][1]  = fmaxf(c2f[n][hc][1] + bb1, 0.f);
                    o1v[n][0] = fmaxf(c2f[n][hc][2] + bb0, 0.f);
                    o1v[n][1] = fmaxf(c2f[n][hc][3] + bb1, 0.f);
                }
                int kb2 = hc >> 1, hf = hc & 1;
#pragma unroll
                for (int m = 0; m < 4; m++) {
                    float i00 = 0.f, i01 = 0.f, i10 = 0.f, i11 = 0.f;
#pragma unroll
                    for (int n = 0; n < 4; n++) {
                        i00 = fmaf(o0[n][0],  cc0[n * 4 + m], i00);
                        i01 = fmaf(o0[n][1],  cc0[n * 4 + m], i01);
                        i10 = fmaf(o1v[n][0], cc1[n * 4 + m], i10);
                        i11 = fmaf(o1v[n][1], cc1[n * 4 + m], i11);
                    }
                    bsplit2(i00, i01, a3h[m][kb2][hf * 2 + 0], a3l[m][kb2][hf * 2 + 0]);
                    bsplit2(i10, i11, a3h[m][kb2][hf * 2 + 1], a3l[m][kb2][hf * 2 + 1]);
                }
            }

            // stage 3
            float c3f[4][4][4];
#pragma unroll
            for (int m = 0; m < 4; m++)
#pragma unroll
                for (int nb = 0; nb < 4; nb++)
#pragma unroll
                    for (int i = 0; i < 4; i++) c3f[m][nb][i] = 0.f;
#pragma unroll
            for (int m = 0; m < 4; m++)
#pragma unroll
                for (int kb = 0; kb < 2; kb++)
#pragma unroll
                    for (int nb = 0; nb < 4; nb++) {
                        uint4 w = w3f[((m * 2 + kb) * 4 + nb) * 32 + lane];
                        mma16816(c3f[m][nb], a3h[m][kb], w.x, w.y);
                        mma16816(c3f[m][nb], a3h[m][kb], w.z, w.w);
                        mma16816(c3f[m][nb], a3l[m][kb], w.x, w.y);
                    }

            // final: relu(+b3), c3 mix, Wf dot, quad reduce
            float c3c0[4], c3c1[4];
            {
                float4 v = *(const float4*)(c3 + (size_t)q0 * 4);
                c3c0[0] = v.x; c3c0[1] = v.y; c3c0[2] = v.z; c3c0[3] = v.w;
                float4 w = *(const float4*)(c3 + (size_t)q1 * 4);
                c3c1[0] = w.x; c3c1[1] = w.y; c3c1[2] = w.z; c3c1[3] = w.w;
            }
            float pa = 0.f, pb = 0.f;
#pragma unroll
            for (int nb = 0; nb < 4; nb++) {
#pragma unroll
                for (int n = 0; n < 4; n++) {
                    float bb0 = b3s[n * 32 + nb * 8 + t * 2], bb1 = b3s[n * 32 + nb * 8 + t * 2 + 1];
                    float q00 = fmaxf(c3f[n][nb][0] + bb0, 0.f);
                    float q01 = fmaxf(c3f[n][nb][1] + bb1, 0.f);
                    float q10 = fmaxf(c3f[n][nb][2] + bb0, 0.f);
                    float q11 = fmaxf(c3f[n][nb][3] + bb1, 0.f);
                    pa = fmaf(fmaf(q00, wfv[nb][0], q01 * wfv[nb][1]), c3c0[n], pa);
                    pb = fmaf(fmaf(q10, wfv[nb][0], q11 * wfv[nb][1]), c3c1[n], pb);
                }
            }
            pa += __shfl_xor_sync(0xffffffffu, pa, 1);
            pa += __shfl_xor_sync(0xffffffffu, pa, 2);
            pb += __shfl_xor_sync(0xffffffffu, pb, 1);
            pb += __shfl_xor_sync(0xffffffffu, pb, 2);
            if (t == 0) {
                if (r[2 * b]     < Btot) out[r[2 * b]]     = pa + bf0;
                if (r[2 * b + 1] < Btot) out[r[2 * b + 1]] = pb + bf0;
            }
        }
    }
}

extern "C" void kernel_launch(void* const* d_in, const int* in_sizes, int n_in,
                              void* d_out, int out_size) {
    const float* x   = (const float*)d_in[0];
    const float* c1  = (const float*)d_in[1];
    const float* c2  = (const float*)d_in[2];
    const float* c3  = (const float*)d_in[3];
    const float* W1  = (const float*)d_in[4];
    const float* b1  = (const float*)d_in[5];
    const float* W2  = (const float*)d_in[6];
    const float* b2  = (const float*)d_in[7];
    const float* W3  = (const float*)d_in[8];
    const float* b3  = (const float*)d_in[9];
    const float* Wf  = (const float*)d_in[10];
    const float* bfp = (const float*)d_in[11];
    int B = in_sizes[0] / KDIM;
    static bool configured = false;
    if (!configured) {
        cudaFuncSetAttribute(moe_kernel, cudaFuncAttributeMaxDynamicSharedMemorySize, SMEM_BYTES);
        configured = true;
    }
    moe_kernel<<<148, 32 * NWARP, SMEM_BYTES>>>(x, c1, c2, c3, W1, b1, W2, b2, W3, b3, Wf, bfp,
                                                (float*)d_out, B);
}

// round 8
// speedup vs baseline: 1.4478x; 1.4469x over previous
#include <cuda_runtime.h>
#include <cuda_fp16.h>
#include <cstdint>

#define KDIM 256
#define NWARP 12

// ---------- helpers ----------
// pack two floats -> half2 (a in low, b in high)
__device__ __forceinline__ uint32_t pkh2(float a, float b) {
    uint32_t r;
    asm("cvt.rn.f16x2.f32 %0, %1, %2;" : "=r"(r) : "f"(b), "f"(a));
    return r;
}
// split two floats into half2 hi + half2 lo (residual)
__device__ __forceinline__ void hsplit2(float a, float b, uint32_t& hi, uint32_t& lo) {
    __half ah = __float2half_rn(a), bh = __float2half_rn(b);
    hi = ((uint32_t)__half_as_ushort(bh) << 16) | (uint32_t)__half_as_ushort(ah);
    lo = pkh2(a - __half2float(ah), b - __half2float(bh));
}
__device__ __forceinline__ void mma16816(float* c, const uint32_t* a, uint32_t b0, uint32_t b1) {
    asm volatile(
        "mma.sync.aligned.m16n8k16.row.col.f32.f16.f16.f32 "
        "{%0,%1,%2,%3},{%4,%5,%6,%7},{%8,%9},{%0,%1,%2,%3};"
        : "+f"(c[0]), "+f"(c[1]), "+f"(c[2]), "+f"(c[3])
        : "r"(a[0]), "r"(a[1]), "r"(a[2]), "r"(a[3]), "r"(b0), "r"(b1));
}

// SMEM layout (bytes)
#define SM_W1F 0          // uint4[16 kb][16 nb][32 lane]  = 131072
#define SM_W2F 131072     // uint4[4 m][2 kb][4 nb][32]    = 16384
#define SM_W3F 147456     // 16384
#define SM_B1  163840
#define SM_B2  164352
#define SM_B3  164864
#define SM_WF  165376
#define SM_BFV 165504
#define SMEM_BYTES 165632

extern __shared__ char smem[];

__global__ void __launch_bounds__(32 * NWARP, 1)
moe_kernel(const float* __restrict__ x,  const float* __restrict__ c1,
           const float* __restrict__ c2, const float* __restrict__ c3,
           const float* __restrict__ W1, const float* __restrict__ b1,
           const float* __restrict__ W2, const float* __restrict__ b2,
           const float* __restrict__ W3, const float* __restrict__ b3,
           const float* __restrict__ Wf, const float* __restrict__ bfp,
           float* __restrict__ out, int Btot) {
    const int tid = threadIdx.x;
    const int wid = tid >> 5;
    const int lane = tid & 31;
    const int g = lane >> 2;   // row within m16 block
    const int t = lane & 3;    // thread-in-group

    uint4* w1f = (uint4*)(smem + SM_W1F);
    uint4* w2f = (uint4*)(smem + SM_W2F);
    uint4* w3f = (uint4*)(smem + SM_W3F);
    float* b1s = (float*)(smem + SM_B1);
    float* b2s = (float*)(smem + SM_B2);
    float* b3s = (float*)(smem + SM_B3);
    float* wfs = (float*)(smem + SM_WF);
    float* bfs = (float*)(smem + SM_BFV);

    // ---- W1 fragments, K-PERMUTED: frag k-slots (t*2,t*2+1 | t*2+8,t*2+9) carry
    //      original k = kb*16 + t*4 + (0,1 | 2,3). A side uses the same permutation. ----
    for (int e = wid; e < 256; e += NWARP) {
        int kb = e >> 4, nb = e & 15;
        const float* wp = W1 + (nb * 8 + g) * 256 + kb * 16 + t * 4;
        uint32_t b0h, b0l, b1h, b1l;
        hsplit2(wp[0], wp[1], b0h, b0l);
        hsplit2(wp[2], wp[3], b1h, b1l);
        w1f[e * 32 + lane] = make_uint4(b0h, b1h, b0l, b1l);
    }
    // ---- W2/W3: identity K-mapping (matches register-local mix outputs) ----
    for (int e = wid; e < 32; e += NWARP) {
        int m = e >> 3, kb = (e >> 2) & 1, nb = e & 3;
        int off = (m * 32 + nb * 8 + g) * 32 + kb * 16 + t * 2;
        {
            const float* wp = W2 + off;
            uint32_t b0h, b0l, b1h, b1l;
            hsplit2(wp[0], wp[1], b0h, b0l);
            hsplit2(wp[8], wp[9], b1h, b1l);
            w2f[e * 32 + lane] = make_uint4(b0h, b1h, b0l, b1l);
        }
        {
            const float* wp = W3 + off;
            uint32_t b0h, b0l, b1h, b1l;
            hsplit2(wp[0], wp[1], b0h, b0l);
            hsplit2(wp[8], wp[9], b1h, b1l);
            w3f[e * 32 + lane] = make_uint4(b0h, b1h, b0l, b1l);
        }
    }
    if (tid < 128) { b1s[tid] = b1[tid]; b2s[tid] = b2[tid]; b3s[tid] = b3[tid]; }
    if (tid < 32 && wid == 0) wfs[tid] = Wf[tid];
    if (tid == 0) bfs[0] = bfp[0];
    __syncthreads();

    float wfv[4][2];
#pragma unroll
    for (int nb = 0; nb < 4; nb++) { wfv[nb][0] = wfs[nb * 8 + t * 2]; wfv[nb][1] = wfs[nb * 8 + t * 2 + 1]; }
    const float bf0 = bfs[0];

    const int gw = blockIdx.x * NWARP + wid;
    const int nunits = (Btot + 15) >> 4;

    for (int u = gw; u < nunits; u += gridDim.x * NWARP) {
        int r0 = u * 16 + g;
        int r1 = r0 + 8;
        int r0c = r0 < Btot ? r0 : Btot - 1;
        int r1c = r1 < Btot ? r1 : Btot - 1;
        const float4* p0 = (const float4*)(x + (size_t)r0c * KDIM + t * 4);
        const float4* p1 = (const float4*)(x + (size_t)r1c * KDIM + t * 4);

        // c1 coeffs (prefetch; latency hidden by stage-1)
        float c1c0[16], c1c1[16];
        {
            const float4* a = (const float4*)(c1 + (size_t)r0c * 16);
            const float4* b = (const float4*)(c1 + (size_t)r1c * 16);
#pragma unroll
            for (int q = 0; q < 4; q++) {
                float4 v = a[q];
                c1c0[4 * q] = v.x; c1c0[4 * q + 1] = v.y; c1c0[4 * q + 2] = v.z; c1c0[4 * q + 3] = v.w;
                float4 w = b[q];
                c1c1[4 * q] = w.x; c1c1[4 * q + 1] = w.y; c1c1[4 * q + 2] = w.z; c1c1[4 * q + 3] = w.w;
            }
        }

        // ---- stage 1: C[16 nb][4] over K=256, fp16 A single, W split 2-pass ----
        float c1f[16][4];
#pragma unroll
        for (int nb = 0; nb < 16; nb++)
#pragma unroll
            for (int i = 0; i < 4; i++) c1f[nb][i] = 0.f;

        // x frags per kb: one float4 per row (k = kb*16 + t*4 .. +3), K-permuted
        float4 f0 = p0[0], f1 = p1[0];
#pragma unroll
        for (int kb = 0; kb < 16; kb++) {
            float4 n0, n1;
            if (kb < 15) { n0 = p0[(kb + 1) * 4]; n1 = p1[(kb + 1) * 4]; }
            uint32_t ah[4];
            ah[0] = pkh2(f0.x, f0.y);
            ah[1] = pkh2(f1.x, f1.y);
            ah[2] = pkh2(f0.z, f0.w);
            ah[3] = pkh2(f1.z, f1.w);
            const uint4* wrow = w1f + kb * 512 + lane;
#pragma unroll
            for (int nb = 0; nb < 16; nb += 2) {
                uint4 w0 = wrow[nb * 32];
                uint4 w1 = wrow[(nb + 1) * 32];
                mma16816(c1f[nb],     ah, w0.x, w0.y);   // A * W_hi
                mma16816(c1f[nb + 1], ah, w1.x, w1.y);
                mma16816(c1f[nb],     ah, w0.z, w0.w);   // A * W_lo
                mma16816(c1f[nb + 1], ah, w1.z, w1.w);
            }
            f0 = n0; f1 = n1;
        }

        // ---- mix1: relu(+b1), c1-mix -> A2 fragments (fp16 single, register-local) ----
        uint32_t a2h[4][2][4];
#pragma unroll
        for (int hc = 0; hc < 4; hc++) {
            float o0[4][2], o1v[4][2];
#pragma unroll
            for (int n = 0; n < 4; n++) {
                int nb = n * 4 + hc;
                float bb0 = b1s[nb * 8 + t * 2], bb1 = b1s[nb * 8 + t * 2 + 1];
                o0[n][0]  = fmaxf(c1f[nb][0] + bb0, 0.f);
                o0[n][1]  = fmaxf(c1f[nb][1] + bb1, 0.f);
                o1v[n][0] = fmaxf(c1f[nb][2] + bb0, 0.f);
                o1v[n][1] = fmaxf(c1f[nb][3] + bb1, 0.f);
            }
            int kb2 = hc >> 1, hf = hc & 1;
#pragma unroll
            for (int m = 0; m < 4; m++) {
                float i00 = 0.f, i01 = 0.f, i10 = 0.f, i11 = 0.f;
#pragma unroll
                for (int n = 0; n < 4; n++) {
                    i00 = fmaf(o0[n][0],  c1c0[n * 4 + m], i00);
                    i01 = fmaf(o0[n][1],  c1c0[n * 4 + m], i01);
                    i10 = fmaf(o1v[n][0], c1c1[n * 4 + m], i10);
                    i11 = fmaf(o1v[n][1], c1c1[n * 4 + m], i11);
                }
                a2h[m][kb2][hf * 2 + 0] = pkh2(i00, i01);
                a2h[m][kb2][hf * 2 + 1] = pkh2(i10, i11);
            }
        }

        // ---- stage 2: 2-pass per (m,kb,nb) ----
        float c2f[4][4][4];
#pragma unroll
        for (int m = 0; m < 4; m++)
#pragma unroll
            for (int nb = 0; nb < 4; nb++)
#pragma unroll
                for (int i = 0; i < 4; i++) c2f[m][nb][i] = 0.f;
#pragma unroll
        for (int m = 0; m < 4; m++)
#pragma unroll
            for (int kb = 0; kb < 2; kb++)
#pragma unroll
                for (int nb = 0; nb < 4; nb += 2) {
                    uint4 w0 = w2f[((m * 2 + kb) * 4 + nb) * 32 + lane];
                    uint4 w1 = w2f[((m * 2 + kb) * 4 + nb + 1) * 32 + lane];
                    mma16816(c2f[m][nb],     a2h[m][kb], w0.x, w0.y);
                    mma16816(c2f[m][nb + 1], a2h[m][kb], w1.x, w1.y);
                    mma16816(c2f[m][nb],     a2h[m][kb], w0.z, w0.w);
                    mma16816(c2f[m][nb + 1], a2h[m][kb], w1.z, w1.w);
                }

        // c2 coeffs
        float c2c0[16], c2c1[16];
        {
            const float4* a = (const float4*)(c2 + (size_t)r0c * 16);
            const float4* b = (const float4*)(c2 + (size_t)r1c * 16);
#pragma unroll
            for (int q = 0; q < 4; q++) {
                float4 v = a[q];
                c2c0[4 * q] = v.x; c2c0[4 * q + 1] = v.y; c2c0[4 * q + 2] = v.z; c2c0[4 * q + 3] = v.w;
                float4 w = b[q];
                c2c1[4 * q] = w.x; c2c1[4 * q + 1] = w.y; c2c1[4 * q + 2] = w.z; c2c1[4 * q + 3] = w.w;
            }
        }

        // ---- mix2 -> A3 ----
        uint32_t a3h[4][2][4];
#pragma unroll
        for (int hc = 0; hc < 4; hc++) {
            float o0[4][2], o1v[4][2];
#pragma unroll
            for (int n = 0; n < 4; n++) {
                float bb0 = b2s[n * 32 + hc * 8 + t * 2], bb1 = b2s[n * 32 + hc * 8 + t * 2 + 1];
                o0[n][0]  = fmaxf(c2f[n][hc][0] + bb0, 0.f);
                o0[n][1]  = fmaxf(c2f[n][hc][1] + bb1, 0.f);
                o1v[n][0] = fmaxf(c2f[n][hc][2] + bb0, 0.f);
                o1v[n][1] = fmaxf(c2f[n][hc][3] + bb1, 0.f);
            }
            int kb2 = hc >> 1, hf = hc & 1;
#pragma unroll
            for (int m = 0; m < 4; m++) {
                float i00 = 0.f, i01 = 0.f, i10 = 0.f, i11 = 0.f;
#pragma unroll
                for (int n = 0; n < 4; n++) {
                    i00 = fmaf(o0[n][0],  c2c0[n * 4 + m], i00);
                    i01 = fmaf(o0[n][1],  c2c0[n * 4 + m], i01);
                    i10 = fmaf(o1v[n][0], c2c1[n * 4 + m], i10);
                    i11 = fmaf(o1v[n][1], c2c1[n * 4 + m], i11);
                }
                a3h[m][kb2][hf * 2 + 0] = pkh2(i00, i01);
                a3h[m][kb2][hf * 2 + 1] = pkh2(i10, i11);
            }
        }

        // ---- stage 3 ----
        float c3f[4][4][4];
#pragma unroll
        for (int m = 0; m < 4; m++)
#pragma unroll
            for (int nb = 0; nb < 4; nb++)
#pragma unroll
                for (int i = 0; i < 4; i++) c3f[m][nb][i] = 0.f;
#pragma unroll
        for (int m = 0; m < 4; m++)
#pragma unroll
            for (int kb = 0; kb < 2; kb++)
#pragma unroll
                for (int nb = 0; nb < 4; nb += 2) {
                    uint4 w0 = w3f[((m * 2 + kb) * 4 + nb) * 32 + lane];
                    uint4 w1 = w3f[((m * 2 + kb) * 4 + nb + 1) * 32 + lane];
                    mma16816(c3f[m][nb],     a3h[m][kb], w0.x, w0.y);
                    mma16816(c3f[m][nb + 1], a3h[m][kb], w1.x, w1.y);
                    mma16816(c3f[m][nb],     a3h[m][kb], w0.z, w0.w);
                    mma16816(c3f[m][nb + 1], a3h[m][kb], w1.z, w1.w);
                }

        // c3 coeffs
        float c3c0[4], c3c1[4];
        {
            float4 v = *(const float4*)(c3 + (size_t)r0c * 4);
            c3c0[0] = v.x; c3c0[1] = v.y; c3c0[2] = v.z; c3c0[3] = v.w;
            float4 w = *(const float4*)(c3 + (size_t)r1c * 4);
            c3c1[0] = w.x; c3c1[1] = w.y; c3c1[2] = w.z; c3c1[3] = w.w;
        }

        // ---- final: relu(+b3), c3 mix, Wf dot, quad reduce ----
        float pa = 0.f, pb = 0.f;
#pragma unroll
        for (int nb = 0; nb < 4; nb++) {
#pragma unroll
            for (int n = 0; n < 4; n++) {
                float bb0 = b3s[n * 32 + nb * 8 + t * 2], bb1 = b3s[n * 32 + nb * 8 + t * 2 + 1];
                float q00 = fmaxf(c3f[n][nb][0] + bb0, 0.f);
                float q01 = fmaxf(c3f[n][nb][1] + bb1, 0.f);
                float q10 = fmaxf(c3f[n][nb][2] + bb0, 0.f);
                float q11 = fmaxf(c3f[n][nb][3] + bb1, 0.f);
                pa = fmaf(fmaf(q00, wfv[nb][0], q01 * wfv[nb][1]), c3c0[n], pa);
                pb = fmaf(fmaf(q10, wfv[nb][0], q11 * wfv[nb][1]), c3c1[n], pb);
            }
        }
        pa += __shfl_xor_sync(0xffffffffu, pa, 1);
        pa += __shfl_xor_sync(0xffffffffu, pa, 2);
        pb += __shfl_xor_sync(0xffffffffu, pb, 1);
        pb += __shfl_xor_sync(0xffffffffu, pb, 2);
        if (t == 0) {
            if (r0 < Btot) out[r0] = pa + bf0;
            if (r1 < Btot) out[r1] = pb + bf0;
        }
    }
}

extern "C" void kernel_launch(void* const* d_in, const int* in_sizes, int n_in,
                              void* d_out, int out_size) {
    const float* x   = (const float*)d_in[0];
    const float* c1  = (const float*)d_in[1];
    const float* c2  = (const float*)d_in[2];
    const float* c3  = (const float*)d_in[3];
    const float* W1  = (const float*)d_in[4];
    const float* b1  = (const float*)d_in[5];
    const float* W2  = (const float*)d_in[6];
    const float* b2  = (const float*)d_in[7];
    const float* W3  = (const float*)d_in[8];
    const float* b3  = (const float*)d_in[9];
    const float* Wf  = (const float*)d_in[10];
    const float* bfp = (const float*)d_in[11];
    int B = in_sizes[0] / KDIM;
    static bool configured = false;
    if (!configured) {
        cudaFuncSetAttribute(moe_kernel, cudaFuncAttributeMaxDynamicSharedMemorySize, SMEM_BYTES);
        configured = true;
    }
    moe_kernel<<<148, 32 * NWARP, SMEM_BYTES>>>(x, c1, c2, c3, W1, b1, W2, b2, W3, b3, Wf, bfp,
                                                (float*)d_out, B);
}

// round 9
// speedup vs baseline: 1.4545x; 1.0046x over previous
#include <cuda_runtime.h>
#include <cuda_fp16.h>
#include <cstdint>

#define KDIM 256
#define NWARP 12

// ---------- helpers ----------
// pack two floats -> half2 (a in low, b in high)
__device__ __forceinline__ uint32_t pkh2(float a, float b) {
    uint32_t r;
    asm("cvt.rn.f16x2.f32 %0, %1, %2;" : "=r"(r) : "f"(b), "f"(a));
    return r;
}
// split two floats into half2 hi + half2 lo (residual)
__device__ __forceinline__ void hsplit2(float a, float b, uint32_t& hi, uint32_t& lo) {
    __half ah = __float2half_rn(a), bh = __float2half_rn(b);
    hi = ((uint32_t)__half_as_ushort(bh) << 16) | (uint32_t)__half_as_ushort(ah);
    lo = pkh2(a - __half2float(ah), b - __half2float(bh));
}
__device__ __forceinline__ void mma16816(float* c, const uint32_t* a, uint32_t b0, uint32_t b1) {
    asm volatile(
        "mma.sync.aligned.m16n8k16.row.col.f32.f16.f16.f32 "
        "{%0,%1,%2,%3},{%4,%5,%6,%7},{%8,%9},{%0,%1,%2,%3};"
        : "+f"(c[0]), "+f"(c[1]), "+f"(c[2]), "+f"(c[3])
        : "r"(a[0]), "r"(a[1]), "r"(a[2]), "r"(a[3]), "r"(b0), "r"(b1));
}

// SMEM layout (bytes)
#define SM_W1F 0          // uint4[16 kb][16 nb][32 lane]  = 131072
#define SM_W2F 131072     // uint4[4 m][2 kb][4 nb][32]    = 16384
#define SM_W3F 147456     // 16384
#define SM_B1  163840
#define SM_B2  164352
#define SM_B3  164864
#define SM_WF  165376
#define SM_BFV 165504
#define SMEM_BYTES 165632

extern __shared__ char smem[];

__global__ void __launch_bounds__(32 * NWARP, 1)
moe_kernel(const float* __restrict__ x,  const float* __restrict__ c1,
           const float* __restrict__ c2, const float* __restrict__ c3,
           const float* __restrict__ W1, const float* __restrict__ b1,
           const float* __restrict__ W2, const float* __restrict__ b2,
           const float* __restrict__ W3, const float* __restrict__ b3,
           const float* __restrict__ Wf, const float* __restrict__ bfp,
           float* __restrict__ out, int Btot) {
    const int tid = threadIdx.x;
    const int wid = tid >> 5;
    const int lane = tid & 31;
    const int g = lane >> 2;   // row within m16 block
    const int t = lane & 3;    // thread-in-group

    uint4* w1f = (uint4*)(smem + SM_W1F);
    uint4* w2f = (uint4*)(smem + SM_W2F);
    uint4* w3f = (uint4*)(smem + SM_W3F);
    float* b1s = (float*)(smem + SM_B1);
    float* b2s = (float*)(smem + SM_B2);
    float* b3s = (float*)(smem + SM_B3);
    float* wfs = (float*)(smem + SM_WF);
    float* bfs = (float*)(smem + SM_BFV);

    // ---- W1 fragments, K-PERMUTED: frag k-slots (t*2,t*2+1 | t*2+8,t*2+9) carry
    //      original k = kb*16 + t*4 + (0,1 | 2,3). A side uses the same permutation. ----
    for (int e = wid; e < 256; e += NWARP) {
        int kb = e >> 4, nb = e & 15;
        const float* wp = W1 + (nb * 8 + g) * 256 + kb * 16 + t * 4;
        uint32_t b0h, b0l, b1h, b1l;
        hsplit2(wp[0], wp[1], b0h, b0l);
        hsplit2(wp[2], wp[3], b1h, b1l);
        w1f[e * 32 + lane] = make_uint4(b0h, b1h, b0l, b1l);
    }
    // ---- W2/W3: identity K-mapping (matches register-local mix outputs) ----
    for (int e = wid; e < 32; e += NWARP) {
        int m = e >> 3, kb = (e >> 2) & 1, nb = e & 3;
        int off = (m * 32 + nb * 8 + g) * 32 + kb * 16 + t * 2;
        {
            const float* wp = W2 + off;
            uint32_t b0h, b0l, b1h, b1l;
            hsplit2(wp[0], wp[1], b0h, b0l);
            hsplit2(wp[8], wp[9], b1h, b1l);
            w2f[e * 32 + lane] = make_uint4(b0h, b1h, b0l, b1l);
        }
        {
            const float* wp = W3 + off;
            uint32_t b0h, b0l, b1h, b1l;
            hsplit2(wp[0], wp[1], b0h, b0l);
            hsplit2(wp[8], wp[9], b1h, b1l);
            w3f[e * 32 + lane] = make_uint4(b0h, b1h, b0l, b1l);
        }
    }
    if (tid < 128) { b1s[tid] = b1[tid]; b2s[tid] = b2[tid]; b3s[tid] = b3[tid]; }
    if (tid < 32 && wid == 0) wfs[tid] = Wf[tid];
    if (tid == 0) bfs[0] = bfp[0];
    __syncthreads();

    float wfv[4][2];
#pragma unroll
    for (int nb = 0; nb < 4; nb++) { wfv[nb][0] = wfs[nb * 8 + t * 2]; wfv[nb][1] = wfs[nb * 8 + t * 2 + 1]; }
    const float bf0 = bfs[0];

    const int gw = blockIdx.x * NWARP + wid;
    const int nunits = (Btot + 15) >> 4;

    for (int u = gw; u < nunits; u += gridDim.x * NWARP) {
        int r0 = u * 16 + g;
        int r1 = r0 + 8;
        int r0c = r0 < Btot ? r0 : Btot - 1;
        int r1c = r1 < Btot ? r1 : Btot - 1;
        const float4* p0 = (const float4*)(x + (size_t)r0c * KDIM + t * 4);
        const float4* p1 = (const float4*)(x + (size_t)r1c * KDIM + t * 4);

        // c1 coeffs (prefetch; latency hidden by stage-1)
        float c1c0[16], c1c1[16];
        {
            const float4* a = (const float4*)(c1 + (size_t)r0c * 16);
            const float4* b = (const float4*)(c1 + (size_t)r1c * 16);
#pragma unroll
            for (int q = 0; q < 4; q++) {
                float4 v = a[q];
                c1c0[4 * q] = v.x; c1c0[4 * q + 1] = v.y; c1c0[4 * q + 2] = v.z; c1c0[4 * q + 3] = v.w;
                float4 w = b[q];
                c1c1[4 * q] = w.x; c1c1[4 * q + 1] = w.y; c1c1[4 * q + 2] = w.z; c1c1[4 * q + 3] = w.w;
            }
        }

        // ---- stage 1: C[16 nb][4] over K=256, fp16 A single, W split 2-pass ----
        float c1f[16][4];
#pragma unroll
        for (int nb = 0; nb < 16; nb++)
#pragma unroll
            for (int i = 0; i < 4; i++) c1f[nb][i] = 0.f;

        // x frags per kb: one float4 per row (k = kb*16 + t*4 .. +3), K-permuted
        float4 f0 = p0[0], f1 = p1[0];
#pragma unroll
        for (int kb = 0; kb < 16; kb++) {
            float4 n0, n1;
            if (kb < 15) { n0 = p0[(kb + 1) * 4]; n1 = p1[(kb + 1) * 4]; }
            uint32_t ah[4];
            ah[0] = pkh2(f0.x, f0.y);
            ah[1] = pkh2(f1.x, f1.y);
            ah[2] = pkh2(f0.z, f0.w);
            ah[3] = pkh2(f1.z, f1.w);
            const uint4* wrow = w1f + kb * 512 + lane;
#pragma unroll
            for (int nb = 0; nb < 16; nb += 2) {
                uint4 w0 = wrow[nb * 32];
                uint4 w1 = wrow[(nb + 1) * 32];
                mma16816(c1f[nb],     ah, w0.x, w0.y);   // A * W_hi
                mma16816(c1f[nb + 1], ah, w1.x, w1.y);
                mma16816(c1f[nb],     ah, w0.z, w0.w);   // A * W_lo
                mma16816(c1f[nb + 1], ah, w1.z, w1.w);
            }
            f0 = n0; f1 = n1;
        }

        // ---- mix1: relu(+b1), c1-mix -> A2 fragments (fp16 single, register-local) ----
        uint32_t a2h[4][2][4];
#pragma unroll
        for (int hc = 0; hc < 4; hc++) {
            float o0[4][2], o1v[4][2];
#pragma unroll
            for (int n = 0; n < 4; n++) {
                int nb = n * 4 + hc;
                float bb0 = b1s[nb * 8 + t * 2], bb1 = b1s[nb * 8 + t * 2 + 1];
                o0[n][0]  = fmaxf(c1f[nb][0] + bb0, 0.f);
                o0[n][1]  = fmaxf(c1f[nb][1] + bb1, 0.f);
                o1v[n][0] = fmaxf(c1f[nb][2] + bb0, 0.f);
                o1v[n][1] = fmaxf(c1f[nb][3] + bb1, 0.f);
            }
            int kb2 = hc >> 1, hf = hc & 1;
#pragma unroll
            for (int m = 0; m < 4; m++) {
                float i00 = 0.f, i01 = 0.f, i10 = 0.f, i11 = 0.f;
#pragma unroll
                for (int n = 0; n < 4; n++) {
                    i00 = fmaf(o0[n][0],  c1c0[n * 4 + m], i00);
                    i01 = fmaf(o0[n][1],  c1c0[n * 4 + m], i01);
                    i10 = fmaf(o1v[n][0], c1c1[n * 4 + m], i10);
                    i11 = fmaf(o1v[n][1], c1c1[n * 4 + m], i11);
                }
                a2h[m][kb2][hf * 2 + 0] = pkh2(i00, i01);
                a2h[m][kb2][hf * 2 + 1] = pkh2(i10, i11);
            }
        }

        // ---- stage 2: 2-pass per (m,kb,nb) ----
        float c2f[4][4][4];
#pragma unroll
        for (int m = 0; m < 4; m++)
#pragma unroll
            for (int nb = 0; nb < 4; nb++)
#pragma unroll
                for (int i = 0; i < 4; i++) c2f[m][nb][i] = 0.f;
#pragma unroll
        for (int m = 0; m < 4; m++)
#pragma unroll
            for (int kb = 0; kb < 2; kb++)
#pragma unroll
                for (int nb = 0; nb < 4; nb += 2) {
                    uint4 w0 = w2f[((m * 2 + kb) * 4 + nb) * 32 + lane];
                    uint4 w1 = w2f[((m * 2 + kb) * 4 + nb + 1) * 32 + lane];
                    mma16816(c2f[m][nb],     a2h[m][kb], w0.x, w0.y);
                    mma16816(c2f[m][nb + 1], a2h[m][kb], w1.x, w1.y);
                    mma16816(c2f[m][nb],     a2h[m][kb], w0.z, w0.w);
                    mma16816(c2f[m][nb + 1], a2h[m][kb], w1.z, w1.w);
                }

        // c2 coeffs
        float c2c0[16], c2c1[16];
        {
            const float4* a = (const float4*)(c2 + (size_t)r0c * 16);
            const float4* b = (const float4*)(c2 + (size_t)r1c * 16);
#pragma unroll
            for (int q = 0; q < 4; q++) {
                float4 v = a[q];
                c2c0[4 * q] = v.x; c2c0[4 * q + 1] = v.y; c2c0[4 * q + 2] = v.z; c2c0[4 * q + 3] = v.w;
                float4 w = b[q];
                c2c1[4 * q] = w.x; c2c1[4 * q + 1] = w.y; c2c1[4 * q + 2] = w.z; c2c1[4 * q + 3] = w.w;
            }
        }

        // ---- mix2 -> A3 ----
        uint32_t a3h[4][2][4];
#pragma unroll
        for (int hc = 0; hc < 4; hc++) {
            float o0[4][2], o1v[4][2];
#pragma unroll
            for (int n = 0; n < 4; n++) {
                float bb0 = b2s[n * 32 + hc * 8 + t * 2], bb1 = b2s[n * 32 + hc * 8 + t * 2 + 1];
                o0[n][0]  = fmaxf(c2f[n][hc][0] + bb0, 0.f);
                o0[n][1]  = fmaxf(c2f[n][hc][1] + bb1, 0.f);
                o1v[n][0] = fmaxf(c2f[n][hc][2] + bb0, 0.f);
                o1v[n][1] = fmaxf(c2f[n][hc][3] + bb1, 0.f);
            }
            int kb2 = hc >> 1, hf = hc & 1;
#pragma unroll
            for (int m = 0; m < 4; m++) {
                float i00 = 0.f, i01 = 0.f, i10 = 0.f, i11 = 0.f;
#pragma unroll
                for (int n = 0; n < 4; n++) {
                    i00 = fmaf(o0[n][0],  c2c0[n * 4 + m], i00);
                    i01 = fmaf(o0[n][1],  c2c0[n * 4 + m], i01);
                    i10 = fmaf(o1v[n][0], c2c1[n * 4 + m], i10);
                    i11 = fmaf(o1v[n][1], c2c1[n * 4 + m], i11);
                }
                a3h[m][kb2][hf * 2 + 0] = pkh2(i00, i01);
                a3h[m][kb2][hf * 2 + 1] = pkh2(i10, i11);
            }
        }

        // ---- stage 3 ----
        float c3f[4][4][4];
#pragma unroll
        for (int m = 0; m < 4; m++)
#pragma unroll
            for (int nb = 0; nb < 4; nb++)
#pragma unroll
                for (int i = 0; i < 4; i++) c3f[m][nb][i] = 0.f;
#pragma unroll
        for (int m = 0; m < 4; m++)
#pragma unroll
            for (int kb = 0; kb < 2; kb++)
#pragma unroll
                for (int nb = 0; nb < 4; nb += 2) {
                    uint4 w0 = w3f[((m * 2 + kb) * 4 + nb) * 32 + lane];
                    uint4 w1 = w3f[((m * 2 + kb) * 4 + nb + 1) * 32 + lane];
                    mma16816(c3f[m][nb],     a3h[m][kb], w0.x, w0.y);
                    mma16816(c3f[m][nb + 1], a3h[m][kb], w1.x, w1.y);
                    mma16816(c3f[m][nb],     a3h[m][kb], w0.z, w0.w);
                    mma16816(c3f[m][nb + 1], a3h[m][kb], w1.z, w1.w);
                }

        // c3 coeffs
        float c3c0[4], c3c1[4];
        {
            float4 v = *(const float4*)(c3 + (size_t)r0c * 4);
            c3c0[0] = v.x; c3c0[1] = v.y; c3c0[2] = v.z; c3c0[3] = v.w;
            float4 w = *(const float4*)(c3 + (size_t)r1c * 4);
            c3c1[0] = w.x; c3c1[1] = w.y; c3c1[2] = w.z; c3c1[3] = w.w;
        }

        // ---- final: relu(+b3), c3 mix, Wf dot, quad reduce ----
        float pa = 0.f, pb = 0.f;
#pragma unroll
        for (int nb = 0; nb < 4; nb++) {
#pragma unroll
            for (int n = 0; n < 4; n++) {
                float bb0 = b3s[n * 32 + nb * 8 + t * 2], bb1 = b3s[n * 32 + nb * 8 + t * 2 + 1];
                float q00 = fmaxf(c3f[n][nb][0] + bb0, 0.f);
                float q01 = fmaxf(c3f[n][nb][1] + bb1, 0.f);
                float q10 = fmaxf(c3f[n][nb][2] + bb0, 0.f);
                float q11 = fmaxf(c3f[n][nb][3] + bb1, 0.f);
                pa = fmaf(fmaf(q00, wfv[nb][0], q01 * wfv[nb][1]), c3c0[n], pa);
                pb = fmaf(fmaf(q10, wfv[nb][0], q11 * wfv[nb][1]), c3c1[n], pb);
            }
        }
        pa += __shfl_xor_sync(0xffffffffu, pa, 1);
        pa += __shfl_xor_sync(0xffffffffu, pa, 2);
        pb += __shfl_xor_sync(0xffffffffu, pb, 1);
        pb += __shfl_xor_sync(0xffffffffu, pb, 2);
        if (t == 0) {
            if (r0 < Btot) out[r0] = pa + bf0;
            if (r1 < Btot) out[r1] = pb + bf0;
        }
    }
}

extern "C" void kernel_launch(void* const* d_in, const int* in_sizes, int n_in,
                              void* d_out, int out_size) {
    const float* x   = (const float*)d_in[0];
    const float* c1  = (const float*)d_in[1];
    const float* c2  = (const float*)d_in[2];
    const float* c3  = (const float*)d_in[3];
    const float* W1  = (const float*)d_in[4];
    const float* b1  = (const float*)d_in[5];
    const float* W2  = (const float*)d_in[6];
    const float* b2  = (const float*)d_in[7];
    const float* W3  = (const float*)d_in[8];
    const float* b3  = (const float*)d_in[9];
    const float* Wf  = (const float*)d_in[10];
    const float* bfp = (const float*)d_in[11];
    int B = in_sizes[0] / KDIM;
    static bool configured = false;
    if (!configured) {
        cudaFuncSetAttribute(moe_kernel, cudaFuncAttributeMaxDynamicSharedMemorySize, SMEM_BYTES);
        configured = true;
    }
    moe_kernel<<<148, 32 * NWARP, SMEM_BYTES>>>(x, c1, c2, c3, W1, b1, W2, b2, W3, b3, Wf, bfp,
                                                (float*)d_out, B);
}

// round 10
// speedup vs baseline: 1.4648x; 1.0071x over previous
#include <cuda_runtime.h>
#include <cuda_fp16.h>
#include <cstdint>

#define KDIM 256
#define NWARP 12

// ---------- helpers ----------
// pack two floats -> half2 (a in low, b in high)
__device__ __forceinline__ uint32_t pkh2(float a, float b) {
    uint32_t r;
    asm("cvt.rn.f16x2.f32 %0, %1, %2;" : "=r"(r) : "f"(b), "f"(a));
    return r;
}
// split two floats into half2 hi + half2 lo (residual)
__device__ __forceinline__ void hsplit2(float a, float b, uint32_t& hi, uint32_t& lo) {
    __half ah = __float2half_rn(a), bh = __float2half_rn(b);
    hi = ((uint32_t)__half_as_ushort(bh) << 16) | (uint32_t)__half_as_ushort(ah);
    lo = pkh2(a - __half2float(ah), b - __half2float(bh));
}
__device__ __forceinline__ void mma16816(float* c, const uint32_t* a, uint32_t b0, uint32_t b1) {
    asm volatile(
        "mma.sync.aligned.m16n8k16.row.col.f32.f16.f16.f32 "
        "{%0,%1,%2,%3},{%4,%5,%6,%7},{%8,%9},{%0,%1,%2,%3};"
        : "+f"(c[0]), "+f"(c[1]), "+f"(c[2]), "+f"(c[3])
        : "r"(a[0]), "r"(a[1]), "r"(a[2]), "r"(a[3]), "r"(b0), "r"(b1));
}

// SMEM layout (bytes)
#define SM_W1F 0          // uint4[16 kb][16 nb][32 lane]  = 131072
#define SM_W2F 131072     // uint4[4 m][2 kb][4 nb][32]    = 16384
#define SM_W3F 147456     // 16384
#define SM_B1  163840
#define SM_B2  164352
#define SM_B3  164864
#define SM_WF  165376
#define SM_BFV 165504
#define SMEM_BYTES 165632

extern __shared__ char smem[];

__global__ void __launch_bounds__(32 * NWARP, 1)
moe_kernel(const float* __restrict__ x,  const float* __restrict__ c1,
           const float* __restrict__ c2, const float* __restrict__ c3,
           const float* __restrict__ W1, const float* __restrict__ b1,
           const float* __restrict__ W2, const float* __restrict__ b2,
           const float* __restrict__ W3, const float* __restrict__ b3,
           const float* __restrict__ Wf, const float* __restrict__ bfp,
           float* __restrict__ out, int Btot) {
    const int tid = threadIdx.x;
    const int wid = tid >> 5;
    const int lane = tid & 31;
    const int g = lane >> 2;   // row within m16 block
    const int t = lane & 3;    // thread-in-group

    uint4* w1f = (uint4*)(smem + SM_W1F);
    uint4* w2f = (uint4*)(smem + SM_W2F);
    uint4* w3f = (uint4*)(smem + SM_W3F);
    float* b1s = (float*)(smem + SM_B1);
    float* b2s = (float*)(smem + SM_B2);
    float* b3s = (float*)(smem + SM_B3);
    float* wfs = (float*)(smem + SM_WF);
    float* bfs = (float*)(smem + SM_BFV);

    // ---- W1 fragments, K-PERMUTED: frag k-slots (t*2,t*2+1 | t*2+8,t*2+9) carry
    //      original k = kb*16 + t*4 + (0,1 | 2,3). A side uses the same permutation. ----
    for (int e = wid; e < 256; e += NWARP) {
        int kb = e >> 4, nb = e & 15;
        const float* wp = W1 + (nb * 8 + g) * 256 + kb * 16 + t * 4;
        uint32_t b0h, b0l, b1h, b1l;
        hsplit2(wp[0], wp[1], b0h, b0l);
        hsplit2(wp[2], wp[3], b1h, b1l);
        w1f[e * 32 + lane] = make_uint4(b0h, b1h, b0l, b1l);
    }
    // ---- W2/W3: identity K-mapping (matches register-local mix outputs) ----
    for (int e = wid; e < 32; e += NWARP) {
        int m = e >> 3, kb = (e >> 2) & 1, nb = e & 3;
        int off = (m * 32 + nb * 8 + g) * 32 + kb * 16 + t * 2;
        {
            const float* wp = W2 + off;
            uint32_t b0h, b0l, b1h, b1l;
            hsplit2(wp[0], wp[1], b0h, b0l);
            hsplit2(wp[8], wp[9], b1h, b1l);
            w2f[e * 32 + lane] = make_uint4(b0h, b1h, b0l, b1l);
        }
        {
            const float* wp = W3 + off;
            uint32_t b0h, b0l, b1h, b1l;
            hsplit2(wp[0], wp[1], b0h, b0l);
            hsplit2(wp[8], wp[9], b1h, b1l);
            w3f[e * 32 + lane] = make_uint4(b0h, b1h, b0l, b1l);
        }
    }
    if (tid < 128) { b1s[tid] = b1[tid]; b2s[tid] = b2[tid]; b3s[tid] = b3[tid]; }
    if (tid < 32 && wid == 0) wfs[tid] = Wf[tid];
    if (tid == 0) bfs[0] = bfp[0];
    __syncthreads();

    float wfv[4][2];
#pragma unroll
    for (int nb = 0; nb < 4; nb++) { wfv[nb][0] = wfs[nb * 8 + t * 2]; wfv[nb][1] = wfs[nb * 8 + t * 2 + 1]; }
    const float bf0 = bfs[0];

    const int gw = blockIdx.x * NWARP + wid;
    const int nunits = (Btot + 15) >> 4;

    for (int u = gw; u < nunits; u += gridDim.x * NWARP) {
        int r0 = u * 16 + g;
        int r1 = r0 + 8;
        int r0c = r0 < Btot ? r0 : Btot - 1;
        int r1c = r1 < Btot ? r1 : Btot - 1;
        const float4* p0 = (const float4*)(x + (size_t)r0c * KDIM + t * 4);
        const float4* p1 = (const float4*)(x + (size_t)r1c * KDIM + t * 4);

        // c1 coeffs (prefetch; latency hidden by stage-1)
        float c1c0[16], c1c1[16];
        {
            const float4* a = (const float4*)(c1 + (size_t)r0c * 16);
            const float4* b = (const float4*)(c1 + (size_t)r1c * 16);
#pragma unroll
            for (int q = 0; q < 4; q++) {
                float4 v = a[q];
                c1c0[4 * q] = v.x; c1c0[4 * q + 1] = v.y; c1c0[4 * q + 2] = v.z; c1c0[4 * q + 3] = v.w;
                float4 w = b[q];
                c1c1[4 * q] = w.x; c1c1[4 * q + 1] = w.y; c1c1[4 * q + 2] = w.z; c1c1[4 * q + 3] = w.w;
            }
        }

        // ---- stage 1: C[16 nb][4] over K=256, fp16 A single, W split 2-pass ----
        float c1f[16][4];
#pragma unroll
        for (int nb = 0; nb < 16; nb++)
#pragma unroll
            for (int i = 0; i < 4; i++) c1f[nb][i] = 0.f;

        // x frags per kb: one float4 per row (k = kb*16 + t*4 .. +3), K-permuted
        float4 f0 = p0[0], f1 = p1[0];
#pragma unroll
        for (int kb = 0; kb < 16; kb++) {
            float4 n0, n1;
            if (kb < 15) { n0 = p0[(kb + 1) * 4]; n1 = p1[(kb + 1) * 4]; }
            uint32_t ah[4];
            ah[0] = pkh2(f0.x, f0.y);
            ah[1] = pkh2(f1.x, f1.y);
            ah[2] = pkh2(f0.z, f0.w);
            ah[3] = pkh2(f1.z, f1.w);
            const uint4* wrow = w1f + kb * 512 + lane;
#pragma unroll
            for (int nb = 0; nb < 16; nb += 2) {
                uint4 w0 = wrow[nb * 32];
                uint4 w1 = wrow[(nb + 1) * 32];
                mma16816(c1f[nb],     ah, w0.x, w0.y);   // A * W_hi
                mma16816(c1f[nb + 1], ah, w1.x, w1.y);
                mma16816(c1f[nb],     ah, w0.z, w0.w);   // A * W_lo
                mma16816(c1f[nb + 1], ah, w1.z, w1.w);
            }
            f0 = n0; f1 = n1;
        }

        // ---- mix1: relu(+b1), c1-mix -> A2 fragments (fp16 single, register-local) ----
        uint32_t a2h[4][2][4];
#pragma unroll
        for (int hc = 0; hc < 4; hc++) {
            float o0[4][2], o1v[4][2];
#pragma unroll
            for (int n = 0; n < 4; n++) {
                int nb = n * 4 + hc;
                float bb0 = b1s[nb * 8 + t * 2], bb1 = b1s[nb * 8 + t * 2 + 1];
                o0[n][0]  = fmaxf(c1f[nb][0] + bb0, 0.f);
                o0[n][1]  = fmaxf(c1f[nb][1] + bb1, 0.f);
                o1v[n][0] = fmaxf(c1f[nb][2] + bb0, 0.f);
                o1v[n][1] = fmaxf(c1f[nb][3] + bb1, 0.f);
            }
            int kb2 = hc >> 1, hf = hc & 1;
#pragma unroll
            for (int m = 0; m < 4; m++) {
                float i00 = 0.f, i01 = 0.f, i10 = 0.f, i11 = 0.f;
#pragma unroll
                for (int n = 0; n < 4; n++) {
                    i00 = fmaf(o0[n][0],  c1c0[n * 4 + m], i00);
                    i01 = fmaf(o0[n][1],  c1c0[n * 4 + m], i01);
                    i10 = fmaf(o1v[n][0], c1c1[n * 4 + m], i10);
                    i11 = fmaf(o1v[n][1], c1c1[n * 4 + m], i11);
                }
                a2h[m][kb2][hf * 2 + 0] = pkh2(i00, i01);
                a2h[m][kb2][hf * 2 + 1] = pkh2(i10, i11);
            }
        }

        // ---- stage 2: 2-pass per (m,kb,nb) ----
        float c2f[4][4][4];
#pragma unroll
        for (int m = 0; m < 4; m++)
#pragma unroll
            for (int nb = 0; nb < 4; nb++)
#pragma unroll
                for (int i = 0; i < 4; i++) c2f[m][nb][i] = 0.f;
#pragma unroll
        for (int m = 0; m < 4; m++)
#pragma unroll
            for (int kb = 0; kb < 2; kb++)
#pragma unroll
                for (int nb = 0; nb < 4; nb += 2) {
                    uint4 w0 = w2f[((m * 2 + kb) * 4 + nb) * 32 + lane];
                    uint4 w1 = w2f[((m * 2 + kb) * 4 + nb + 1) * 32 + lane];
                    mma16816(c2f[m][nb],     a2h[m][kb], w0.x, w0.y);
                    mma16816(c2f[m][nb + 1], a2h[m][kb], w1.x, w1.y);
                    mma16816(c2f[m][nb],     a2h[m][kb], w0.z, w0.w);
                    mma16816(c2f[m][nb + 1], a2h[m][kb], w1.z, w1.w);
                }

        // c2 coeffs
        float c2c0[16], c2c1[16];
        {
            const float4* a = (const float4*)(c2 + (size_t)r0c * 16);
            const float4* b = (const float4*)(c2 + (size_t)r1c * 16);
#pragma unroll
            for (int q = 0; q < 4; q++) {
                float4 v = a[q];
                c2c0[4 * q] = v.x; c2c0[4 * q + 1] = v.y; c2c0[4 * q + 2] = v.z; c2c0[4 * q + 3] = v.w;
                float4 w = b[q];
                c2c1[4 * q] = w.x; c2c1[4 * q + 1] = w.y; c2c1[4 * q + 2] = w.z; c2c1[4 * q + 3] = w.w;
            }
        }

        // ---- mix2 -> A3 ----
        uint32_t a3h[4][2][4];
#pragma unroll
        for (int hc = 0; hc < 4; hc++) {
            float o0[4][2], o1v[4][2];
#pragma unroll
            for (int n = 0; n < 4; n++) {
                float bb0 = b2s[n * 32 + hc * 8 + t * 2], bb1 = b2s[n * 32 + hc * 8 + t * 2 + 1];
                o0[n][0]  = fmaxf(c2f[n][hc][0] + bb0, 0.f);
                o0[n][1]  = fmaxf(c2f[n][hc][1] + bb1, 0.f);
                o1v[n][0] = fmaxf(c2f[n][hc][2] + bb0, 0.f);
                o1v[n][1] = fmaxf(c2f[n][hc][3] + bb1, 0.f);
            }
            int kb2 = hc >> 1, hf = hc & 1;
#pragma unroll
            for (int m = 0; m < 4; m++) {
                float i00 = 0.f, i01 = 0.f, i10 = 0.f, i11 = 0.f;
#pragma unroll
                for (int n = 0; n < 4; n++) {
                    i00 = fmaf(o0[n][0],  c2c0[n * 4 + m], i00);
                    i01 = fmaf(o0[n][1],  c2c0[n * 4 + m], i01);
                    i10 = fmaf(o1v[n][0], c2c1[n * 4 + m], i10);
                    i11 = fmaf(o1v[n][1], c2c1[n * 4 + m], i11);
                }
                a3h[m][kb2][hf * 2 + 0] = pkh2(i00, i01);
                a3h[m][kb2][hf * 2 + 1] = pkh2(i10, i11);
            }
        }

        // ---- stage 3 ----
        float c3f[4][4][4];
#pragma unroll
        for (int m = 0; m < 4; m++)
#pragma unroll
            for (int nb = 0; nb < 4; nb++)
#pragma unroll
                for (int i = 0; i < 4; i++) c3f[m][nb][i] = 0.f;
#pragma unroll
        for (int m = 0; m < 4; m++)
#pragma unroll
            for (int kb = 0; kb < 2; kb++)
#pragma unroll
                for (int nb = 0; nb < 4; nb += 2) {
                    uint4 w0 = w3f[((m * 2 + kb) * 4 + nb) * 32 + lane];
                    uint4 w1 = w3f[((m * 2 + kb) * 4 + nb + 1) * 32 + lane];
                    mma16816(c3f[m][nb],     a3h[m][kb], w0.x, w0.y);
                    mma16816(c3f[m][nb + 1], a3h[m][kb], w1.x, w1.y);
                    mma16816(c3f[m][nb],     a3h[m][kb], w0.z, w0.w);
                    mma16816(c3f[m][nb + 1], a3h[m][kb], w1.z, w1.w);
                }

        // c3 coeffs
        float c3c0[4], c3c1[4];
        {
            float4 v = *(const float4*)(c3 + (size_t)r0c * 4);
            c3c0[0] = v.x; c3c0[1] = v.y; c3c0[2] = v.z; c3c0[3] = v.w;
            float4 w = *(const float4*)(c3 + (size_t)r1c * 4);
            c3c1[0] = w.x; c3c1[1] = w.y; c3c1[2] = w.z; c3c1[3] = w.w;
        }

        // ---- final: relu(+b3), c3 mix, Wf dot, quad reduce ----
        float pa = 0.f, pb = 0.f;
#pragma unroll
        for (int nb = 0; nb < 4; nb++) {
#pragma unroll
            for (int n = 0; n < 4; n++) {
                float bb0 = b3s[n * 32 + nb * 8 + t * 2], bb1 = b3s[n * 32 + nb * 8 + t * 2 + 1];
                float q00 = fmaxf(c3f[n][nb][0] + bb0, 0.f);
                float q01 = fmaxf(c3f[n][nb][1] + bb1, 0.f);
                float q10 = fmaxf(c3f[n][nb][2] + bb0, 0.f);
                float q11 = fmaxf(c3f[n][nb][3] + bb1, 0.f);
                pa = fmaf(fmaf(q00, wfv[nb][0], q01 * wfv[nb][1]), c3c0[n], pa);
                pb = fmaf(fmaf(q10, wfv[nb][0], q11 * wfv[nb][1]), c3c1[n], pb);
            }
        }
        pa += __shfl_xor_sync(0xffffffffu, pa, 1);
        pa += __shfl_xor_sync(0xffffffffu, pa, 2);
        pb += __shfl_xor_sync(0xffffffffu, pb, 1);
        pb += __shfl_xor_sync(0xffffffffu, pb, 2);
        if (t == 0) {
            if (r0 < Btot) out[r0] = pa + bf0;
            if (r1 < Btot) out[r1] = pb + bf0;
        }
    }
}

extern "C" void kernel_launch(void* const* d_in, const int* in_sizes, int n_in,
                              void* d_out, int out_size) {
    const float* x   = (const float*)d_in[0];
    const float* c1  = (const float*)d_in[1];
    const float* c2  = (const float*)d_in[2];
    const float* c3  = (const float*)d_in[3];
    const float* W1  = (const float*)d_in[4];
    const float* b1  = (const float*)d_in[5];
    const float* W2  = (const float*)d_in[6];
    const float* b2  = (const float*)d_in[7];
    const float* W3  = (const float*)d_in[8];
    const float* b3  = (const float*)d_in[9];
    const float* Wf  = (const float*)d_in[10];
    const float* bfp = (const float*)d_in[11];
    int B = in_sizes[0] / KDIM;
    static bool configured = false;
    if (!configured) {
        cudaFuncSetAttribute(moe_kernel, cudaFuncAttributeMaxDynamicSharedMemorySize, SMEM_BYTES);
        configured = true;
    }
    moe_kernel<<<148, 32 * NWARP, SMEM_BYTES>>>(x, c1, c2, c3, W1, b1, W2, b2, W3, b3, Wf, bfp,
                                                (float*)d_out, B);
}